// round 8
// baseline (speedup 1.0000x reference)
#include <cuda_runtime.h>
#include <cuda_bf16.h>
#include <cstdint>

typedef unsigned long long u64;

__device__ __forceinline__ u64 pk2(float lo, float hi) {
    u64 d; asm("mov.b64 %0, {%1, %2};" : "=l"(d) : "f"(lo), "f"(hi)); return d;
}
__device__ __forceinline__ void upk2(u64 v, float& lo, float& hi) {
    asm("mov.b64 {%0, %1}, %2;" : "=f"(lo), "=f"(hi) : "l"(v));
}
__device__ __forceinline__ u64 fma2(u64 a, u64 b, u64 c) {
    u64 d; asm("fma.rn.f32x2 %0, %1, %2, %3;" : "=l"(d) : "l"(a), "l"(b), "l"(c)); return d;
}

__device__ __forceinline__ uint32_t smem_u32(const void* p) {
    uint32_t a;
    asm("{ .reg .u64 tmp; cvta.to.shared.u64 tmp, %1; cvt.u32.u64 %0, tmp; }"
        : "=r"(a) : "l"(p));
    return a;
}

__device__ __forceinline__ int q_of(float t) {
    // t*1024 is exact in fp32 (power-of-two scale), so truncation == floor,
    // matching the reference's interval comparisons bit-exactly.
    int q = (int)(t * 1024.0f);
    q = q < 0 ? 0 : (q > 1023 ? 1023 : q);
    return q;
}

// Fused: bulk-async stage t into smem (overlapped with the LUT build), build
// the 1024-entry LUT (one quad per thread), gather through smem, stage output
// in smem, and drain it with a single bulk-async store per block.
__global__ void __launch_bounds__(256) haar_fused(const float* __restrict__ t,
                                                  const float* __restrict__ W1,
                                                  const float* __restrict__ b1,
                                                  const float* __restrict__ W2,
                                                  const float* __restrict__ b2,
                                                  const float* __restrict__ W3,
                                                  const float* __restrict__ b3,
                                                  float* __restrict__ out,
                                                  int n) {
    __shared__ float4 tab[1024];        // 16 KB LUT
    __shared__ float4 tin[256];         // 4 KB staged input (1024 points)
    __shared__ float4 ostage[768];      // 12 KB staged output
    __shared__ u64 w3s[12];
    __shared__ u64 mbar;

    int tid = threadIdx.x;
    int i = blockIdx.x * blockDim.x + tid;
    int n4 = n >> 2;

    int blk_begin = blockIdx.x * blockDim.x;
    bool full_block = (blk_begin + (int)blockDim.x) <= n4;

    // ---- Kick off bulk-async load of this block's t slice ----
    uint32_t mbar_a = smem_u32(&mbar);
    if (full_block) {
        if (tid == 0) {
            asm volatile("mbarrier.init.shared.b64 [%0], 1;" :: "r"(mbar_a) : "memory");
            asm volatile("fence.proxy.async.shared::cta;" ::: "memory");
            asm volatile("mbarrier.arrive.expect_tx.shared.b64 _, [%0], %1;"
                         :: "r"(mbar_a), "r"(4096u) : "memory");
            const float4* src = reinterpret_cast<const float4*>(t) + blk_begin;
            asm volatile(
                "cp.async.bulk.shared::cluster.global.mbarrier::complete_tx::bytes "
                "[%0], [%1], %2, [%3];"
                :: "r"(smem_u32(tin)), "l"(src), "r"(4096u), "r"(mbar_a)
                : "memory");
        }
    }

    // ---- Fallback prefetch for a partial block ----
    float4 tv = make_float4(0.f, 0.f, 0.f, 0.f);
    if (!full_block && i < n4) tv = reinterpret_cast<const float4*>(t)[i];
    int tail_start = n4 << 2;
    int tail_n = n - tail_start;
    float t_tail = 0.f;
    if (i < tail_n) t_tail = t[tail_start + i];

    // ---- Stage packed W3 pairs into smem ----
    if (tid < 12) {
        int f = tid % 3, kk = tid / 3;
        w3s[f * 4 + kk] = pk2(W3[(2 * kk) * 3 + f], W3[(2 * kk + 1) * 3 + f]);
    }

    // ---- Per-thread register preloads ----
    const ulonglong2* w2v = reinterpret_cast<const ulonglong2*>(W2);
    u64 w2p[32];
#pragma unroll
    for (int r = 0; r < 16; r++) { ulonglong2 v = w2v[r]; w2p[2*r] = v.x; w2p[2*r+1] = v.y; }

    const ulonglong2* b1v = reinterpret_cast<const ulonglong2*>(b1);
    u64 b1p[4];
    { ulonglong2 v0 = b1v[0], v1 = b1v[1]; b1p[0]=v0.x; b1p[1]=v0.y; b1p[2]=v1.x; b1p[3]=v1.y; }

    const ulonglong2* b2v = reinterpret_cast<const ulonglong2*>(b2);
    u64 b2p[4];
    { ulonglong2 v0 = b2v[0], v1 = b2v[1]; b2p[0]=v0.x; b2p[1]=v0.y; b2p[2]=v1.x; b2p[3]=v1.y; }

    float b3r[3];
#pragma unroll
    for (int f = 0; f < 3; f++) b3r[f] = b3[f];

    __syncthreads();   // w3s + mbarrier init visible

    const ulonglong2* w1v = reinterpret_cast<const ulonglong2*>(W1);

    // ---- Build: ONE quad (entries 4g..4g+3) per thread ----
    {
        int g = tid;

        u64 base2[4];
#pragma unroll
        for (int h = 0; h < 4; h++) base2[h] = b1p[h];

#pragma unroll
        for (int j = 0; j < 8; j++) {
            int k   = g >> (8 - j);
            int row = (1 << j) - 1 + k;
            float s = ((g >> (7 - j)) & 1) ? -1.0f : 1.0f;
            u64 s2 = pk2(s, s);
            ulonglong2 r0 = __ldg(w1v + row * 2);
            ulonglong2 r1 = __ldg(w1v + row * 2 + 1);
            base2[0] = fma2(s2, r0.x, base2[0]);
            base2[1] = fma2(s2, r0.y, base2[1]);
            base2[2] = fma2(s2, r1.x, base2[2]);
            base2[3] = fma2(s2, r1.y, base2[3]);
        }

        ulonglong2 a0 = __ldg(w1v + (255 + g) * 2);
        ulonglong2 a1 = __ldg(w1v + (255 + g) * 2 + 1);
        u64 r8[4]  = { a0.x, a0.y, a1.x, a1.y };
        ulonglong2 c0 = __ldg(w1v + (511 + 2 * g) * 2);
        ulonglong2 c1 = __ldg(w1v + (511 + 2 * g) * 2 + 1);
        u64 r9a[4] = { c0.x, c0.y, c1.x, c1.y };
        ulonglong2 d0 = __ldg(w1v + (512 + 2 * g) * 2);
        ulonglong2 d1 = __ldg(w1v + (512 + 2 * g) * 2 + 1);
        u64 r9b[4] = { d0.x, d0.y, d1.x, d1.y };

#pragma unroll
        for (int c = 0; c < 4; c++) {
            float s8 = (c & 2) ? -1.0f : 1.0f;
            float s9 = (c & 1) ? -1.0f : 1.0f;
            u64 s8p = pk2(s8, s8);
            u64 s9p = pk2(s9, s9);
            const u64* r9 = (c & 2) ? r9b : r9a;

            u64 bc[8];
#pragma unroll
            for (int h = 0; h < 4; h++) {
                u64 a2 = fma2(s8p, r8[h], base2[h]);
                a2 = fma2(s9p, r9[h], a2);
                float lo, hi; upk2(a2, lo, hi);
                lo = fmaxf(lo, 0.0f); hi = fmaxf(hi, 0.0f);
                bc[2*h]   = pk2(lo, lo);
                bc[2*h+1] = pk2(hi, hi);
            }

            u64 h2p[4];
#pragma unroll
            for (int kk = 0; kk < 4; kk++) h2p[kk] = b2p[kk];
#pragma unroll
            for (int h = 0; h < 8; h++) {
#pragma unroll
                for (int kk = 0; kk < 4; kk++)
                    h2p[kk] = fma2(bc[h], w2p[h * 4 + kk], h2p[kk]);
            }
#pragma unroll
            for (int kk = 0; kk < 4; kk++) {
                float lo, hi; upk2(h2p[kk], lo, hi);
                h2p[kk] = pk2(fmaxf(lo, 0.0f), fmaxf(hi, 0.0f));
            }

            float o[3];
#pragma unroll
            for (int f = 0; f < 3; f++) {
                u64 acc = pk2(b3r[f], 0.0f);
#pragma unroll
                for (int kk = 0; kk < 4; kk++)
                    acc = fma2(h2p[kk], w3s[f * 4 + kk], acc);
                float lo, hi; upk2(acc, lo, hi);
                o[f] = lo + hi;
            }

            tab[4 * g + c] = make_float4(o[0], o[1], o[2], 0.0f);
        }
    }

    __syncthreads();   // tab complete

    if (full_block) {
        // Wait for the bulk t load (long since complete — overlapped w/ build).
        {
            uint32_t done;
            asm volatile(
                "{\n\t.reg .pred p;\n\t"
                "mbarrier.try_wait.parity.shared.b64 p, [%1], 0;\n\t"
                "selp.b32 %0, 1, 0, p;\n\t}"
                : "=r"(done) : "r"(mbar_a) : "memory");
            while (!done) {
                asm volatile(
                    "{\n\t.reg .pred p;\n\t"
                    "mbarrier.try_wait.parity.shared.b64 p, [%1], 0;\n\t"
                    "selp.b32 %0, 1, 0, p;\n\t}"
                    : "=r"(done) : "r"(mbar_a) : "memory");
            }
        }
        __syncthreads();

        float4 v = tin[tid];
        float4 r0 = tab[q_of(v.x)];
        float4 r1 = tab[q_of(v.y)];
        float4 r2 = tab[q_of(v.z)];
        float4 r3 = tab[q_of(v.w)];

        ostage[3 * tid + 0] = make_float4(r0.x, r0.y, r0.z, r1.x);
        ostage[3 * tid + 1] = make_float4(r1.y, r1.z, r2.x, r2.y);
        ostage[3 * tid + 2] = make_float4(r2.z, r3.x, r3.y, r3.z);

        // Make smem writes visible to the async proxy, then one bulk store.
        asm volatile("fence.proxy.async.shared::cta;" ::: "memory");
        __syncthreads();

        if (tid == 0) {
            float4* dst = reinterpret_cast<float4*>(out) + 3 * blk_begin;
            asm volatile(
                "cp.async.bulk.global.shared::cta.bulk_group [%0], [%1], %2;"
                :: "l"(dst), "r"(smem_u32(ostage)), "r"(12288u)
                : "memory");
            asm volatile("cp.async.bulk.commit_group;" ::: "memory");
            asm volatile("cp.async.bulk.wait_group 0;" ::: "memory");
        }
    } else {
        // Partial block: direct path.
        float4* o4 = reinterpret_cast<float4*>(out);
        if (i < n4) {
            float4 r0 = tab[q_of(tv.x)];
            float4 r1 = tab[q_of(tv.y)];
            float4 r2 = tab[q_of(tv.z)];
            float4 r3 = tab[q_of(tv.w)];
            o4[3 * i + 0] = make_float4(r0.x, r0.y, r0.z, r1.x);
            o4[3 * i + 1] = make_float4(r1.y, r1.z, r2.x, r2.y);
            o4[3 * i + 2] = make_float4(r2.z, r3.x, r3.y, r3.z);
        }
    }

    // Scalar tail (n not divisible by 4) — dead for n = 131072 but kept correct.
    if (i < tail_n) {
        int pidx = tail_start + i;
        float4 r = tab[q_of(t_tail)];
        out[3 * pidx + 0] = r.x;
        out[3 * pidx + 1] = r.y;
        out[3 * pidx + 2] = r.z;
    }
}

extern "C" void kernel_launch(void* const* d_in, const int* in_sizes, int n_in,
                              void* d_out, int out_size) {
    const float* t  = (const float*)d_in[0];
    const float* W1 = (const float*)d_in[1];
    const float* b1 = (const float*)d_in[2];
    const float* W2 = (const float*)d_in[3];
    const float* b2 = (const float*)d_in[4];
    const float* W3 = (const float*)d_in[5];
    const float* b3 = (const float*)d_in[6];
    float* out = (float*)d_out;

    int n = in_sizes[0];  // B*T points

    int n4 = n >> 2;
    int threads = 256;
    int blocks = (n4 + threads - 1) / threads;
    if (blocks < 1) blocks = 1;
    haar_fused<<<blocks, threads>>>(t, W1, b1, W2, b2, W3, b3, out, n);
}

// round 10
// speedup vs baseline: 1.1354x; 1.1354x over previous
#include <cuda_runtime.h>
#include <cuda_bf16.h>
#include <cstdint>

typedef unsigned long long u64;

__device__ __forceinline__ u64 pk2(float lo, float hi) {
    u64 d; asm("mov.b64 %0, {%1, %2};" : "=l"(d) : "f"(lo), "f"(hi)); return d;
}
__device__ __forceinline__ void upk2(u64 v, float& lo, float& hi) {
    asm("mov.b64 {%0, %1}, %2;" : "=f"(lo), "=f"(hi) : "l"(v));
}
__device__ __forceinline__ u64 fma2(u64 a, u64 b, u64 c) {
    u64 d; asm("fma.rn.f32x2 %0, %1, %2, %3;" : "=l"(d) : "l"(a), "l"(b), "l"(c)); return d;
}

__device__ __forceinline__ int q_of(float t) {
    // t*1024 is exact in fp32 (power-of-two scale), so truncation == floor,
    // matching the reference's interval comparisons bit-exactly.
    int q = (int)(t * 1024.0f);
    q = q < 0 ? 0 : (q > 1023 ? 1023 : q);
    return q;
}

// Fused: each block builds the 1024-entry LUT in shared memory — one QUAD of
// entries (q = 4g..4g+3) per thread — then applies it. Output goes through a
// shared-memory stage so the global stores are fully coalesced.
__global__ void __launch_bounds__(256) haar_fused(const float* __restrict__ t,
                                                  const float* __restrict__ W1,
                                                  const float* __restrict__ b1,
                                                  const float* __restrict__ W2,
                                                  const float* __restrict__ b2,
                                                  const float* __restrict__ W3,
                                                  const float* __restrict__ b3,
                                                  float* __restrict__ out,
                                                  int n) {
    __shared__ float4 tab[1024];      // 16 KB LUT
    __shared__ float4 ostage[768];    // 12 KB output stage
    __shared__ u64 w3s[12];           // w3s[f*4+kk] = (W3[2kk][f], W3[2kk+1][f])

    int tid = threadIdx.x;
    int i = blockIdx.x * blockDim.x + tid;
    int n4 = n >> 2;
    int blk_begin = blockIdx.x * blockDim.x;
    bool full_block = (blk_begin + (int)blockDim.x) <= n4;

    // ---- Prefetch this thread's input points (latency hides behind build) ----
    const float4* t4 = reinterpret_cast<const float4*>(t);
    float4 tv = make_float4(0.f, 0.f, 0.f, 0.f);
    if (i < n4) tv = t4[i];
    int tail_start = n4 << 2;
    int tail_n = n - tail_start;
    float t_tail = 0.f;
    if (i < tail_n) t_tail = t[tail_start + i];

    // ---- Stage packed W3 pairs into smem ----
    if (tid < 12) {
        int f = tid % 3, kk = tid / 3;
        w3s[f * 4 + kk] = pk2(W3[(2 * kk) * 3 + f], W3[(2 * kk + 1) * 3 + f]);
    }

    // ---- Per-thread register preloads ----
    const ulonglong2* w2v = reinterpret_cast<const ulonglong2*>(W2);
    u64 w2p[32];
#pragma unroll
    for (int r = 0; r < 16; r++) { ulonglong2 v = w2v[r]; w2p[2*r] = v.x; w2p[2*r+1] = v.y; }

    const ulonglong2* b1v = reinterpret_cast<const ulonglong2*>(b1);
    u64 b1p[4];
    { ulonglong2 v0 = b1v[0], v1 = b1v[1]; b1p[0]=v0.x; b1p[1]=v0.y; b1p[2]=v1.x; b1p[3]=v1.y; }

    const ulonglong2* b2v = reinterpret_cast<const ulonglong2*>(b2);
    u64 b2p[4];
    { ulonglong2 v0 = b2v[0], v1 = b2v[1]; b2p[0]=v0.x; b2p[1]=v0.y; b2p[2]=v1.x; b2p[3]=v1.y; }

    float b3r[3];
#pragma unroll
    for (int f = 0; f < 3; f++) b3r[f] = b3[f];

    __syncthreads();   // w3s visible

    const ulonglong2* w1v = reinterpret_cast<const ulonglong2*>(W1);

    // ---- Build: ONE quad (entries 4g..4g+3) per thread, g = tid (0..255) ----
    {
        int g = tid;

        u64 base2[4];
#pragma unroll
        for (int h = 0; h < 4; h++) base2[h] = b1p[h];

        // Levels 0..7: rows AND signs shared by the whole quad.
#pragma unroll
        for (int j = 0; j < 8; j++) {
            int k   = g >> (8 - j);
            int row = (1 << j) - 1 + k;
            float s = ((g >> (7 - j)) & 1) ? -1.0f : 1.0f;
            u64 s2 = pk2(s, s);
            ulonglong2 r0 = __ldg(w1v + row * 2);
            ulonglong2 r1 = __ldg(w1v + row * 2 + 1);
            base2[0] = fma2(s2, r0.x, base2[0]);
            base2[1] = fma2(s2, r0.y, base2[1]);
            base2[2] = fma2(s2, r1.x, base2[2]);
            base2[3] = fma2(s2, r1.y, base2[3]);
        }

        // Level-8 row (shared; sign +,+,-,- over c) and two level-9 rows.
        ulonglong2 a0 = __ldg(w1v + (255 + g) * 2);
        ulonglong2 a1 = __ldg(w1v + (255 + g) * 2 + 1);
        u64 r8[4]  = { a0.x, a0.y, a1.x, a1.y };
        ulonglong2 c0 = __ldg(w1v + (511 + 2 * g) * 2);
        ulonglong2 c1 = __ldg(w1v + (511 + 2 * g) * 2 + 1);
        u64 r9a[4] = { c0.x, c0.y, c1.x, c1.y };
        ulonglong2 d0 = __ldg(w1v + (512 + 2 * g) * 2);
        ulonglong2 d1 = __ldg(w1v + (512 + 2 * g) * 2 + 1);
        u64 r9b[4] = { d0.x, d0.y, d1.x, d1.y };

#pragma unroll
        for (int c = 0; c < 4; c++) {
            float s8 = (c & 2) ? -1.0f : 1.0f;
            float s9 = (c & 1) ? -1.0f : 1.0f;
            u64 s8p = pk2(s8, s8);
            u64 s9p = pk2(s9, s9);
            const u64* r9 = (c & 2) ? r9b : r9a;

            // acc = base + s8*r8 + s9*r9; ReLU; broadcast lanes into pairs.
            u64 bc[8];
#pragma unroll
            for (int h = 0; h < 4; h++) {
                u64 a2 = fma2(s8p, r8[h], base2[h]);
                a2 = fma2(s9p, r9[h], a2);
                float lo, hi; upk2(a2, lo, hi);
                lo = fmaxf(lo, 0.0f); hi = fmaxf(hi, 0.0f);
                bc[2*h]   = pk2(lo, lo);
                bc[2*h+1] = pk2(hi, hi);
            }

            // Layer 2: h2 pairs (k, k+1); W2 pairs in registers.
            u64 h2p[4];
#pragma unroll
            for (int kk = 0; kk < 4; kk++) h2p[kk] = b2p[kk];
#pragma unroll
            for (int h = 0; h < 8; h++) {
#pragma unroll
                for (int kk = 0; kk < 4; kk++)
                    h2p[kk] = fma2(bc[h], w2p[h * 4 + kk], h2p[kk]);
            }
#pragma unroll
            for (int kk = 0; kk < 4; kk++) {
                float lo, hi; upk2(h2p[kk], lo, hi);
                h2p[kk] = pk2(fmaxf(lo, 0.0f), fmaxf(hi, 0.0f));
            }

            // Layer 3: packed dot over k-pairs + horizontal add.
            float o[3];
#pragma unroll
            for (int f = 0; f < 3; f++) {
                u64 acc = pk2(b3r[f], 0.0f);
#pragma unroll
                for (int kk = 0; kk < 4; kk++)
                    acc = fma2(h2p[kk], w3s[f * 4 + kk], acc);
                float lo, hi; upk2(acc, lo, hi);
                o[f] = lo + hi;
            }

            tab[4 * g + c] = make_float4(o[0], o[1], o[2], 0.0f);
        }
    }

    __syncthreads();

    // ---- Apply: gather 4 points, stage in smem, store coalesced ----
    float4* o4 = reinterpret_cast<float4*>(out);
    if (full_block) {
        float4 r0 = tab[q_of(tv.x)];
        float4 r1 = tab[q_of(tv.y)];
        float4 r2 = tab[q_of(tv.z)];
        float4 r3 = tab[q_of(tv.w)];

        ostage[3 * tid + 0] = make_float4(r0.x, r0.y, r0.z, r1.x);
        ostage[3 * tid + 1] = make_float4(r1.y, r1.z, r2.x, r2.y);
        ostage[3 * tid + 2] = make_float4(r2.z, r3.x, r3.y, r3.z);
        __syncthreads();

        float4* dst = o4 + 3 * blk_begin;
#pragma unroll
        for (int r = 0; r < 3; r++)
            dst[tid + 256 * r] = ostage[tid + 256 * r];
    } else if (i < n4) {
        float4 r0 = tab[q_of(tv.x)];
        float4 r1 = tab[q_of(tv.y)];
        float4 r2 = tab[q_of(tv.z)];
        float4 r3 = tab[q_of(tv.w)];
        o4[3 * i + 0] = make_float4(r0.x, r0.y, r0.z, r1.x);
        o4[3 * i + 1] = make_float4(r1.y, r1.z, r2.x, r2.y);
        o4[3 * i + 2] = make_float4(r2.z, r3.x, r3.y, r3.z);
    }

    // Scalar tail (n not divisible by 4) — dead for n = 131072 but kept correct.
    if (i < tail_n) {
        int pidx = tail_start + i;
        float4 r = tab[q_of(t_tail)];
        out[3 * pidx + 0] = r.x;
        out[3 * pidx + 1] = r.y;
        out[3 * pidx + 2] = r.z;
    }
}

extern "C" void kernel_launch(void* const* d_in, const int* in_sizes, int n_in,
                              void* d_out, int out_size) {
    const float* t  = (const float*)d_in[0];
    const float* W1 = (const float*)d_in[1];
    const float* b1 = (const float*)d_in[2];
    const float* W2 = (const float*)d_in[3];
    const float* b2 = (const float*)d_in[4];
    const float* W3 = (const float*)d_in[5];
    const float* b3 = (const float*)d_in[6];
    float* out = (float*)d_out;

    int n = in_sizes[0];  // B*T points

    int n4 = n >> 2;
    int threads = 256;
    int blocks = (n4 + threads - 1) / threads;
    if (blocks < 1) blocks = 1;
    haar_fused<<<blocks, threads>>>(t, W1, b1, W2, b2, W3, b3, out, n);
}